// round 2
// baseline (speedup 1.0000x reference)
#include <cuda_runtime.h>
#include <math.h>

// Problem constants (from reference: x[16,64,256,256] f32, w[1,2,3,3] f32)
#define B_  16
#define C_  64
#define H_  256
#define W_  256
#define TH  32
#define TW  32
#define HH  (TH + 2)
#define HW_ (TW + 2)
#define NPIX (HH * HW_)          // 1156 halo pixels
#define NT  256
#define KPP ((NPIX + NT - 1) / NT)  // 5 halo pixels per thread

// Dynamic-SMEM padding to cap residency at exactly 2 blocks/SM:
// static ~13KB + 80KB dynamic = ~93KB/block -> 2 blocks fit (186KB <= 228KB),
// 3 would need <=76KB. Keeps concurrent L2 working set ~87MB < 126MB L2.
#define SMEM_PAD (80 * 1024)

__global__ void __launch_bounds__(NT)
spatial_attention_kernel(const float* __restrict__ x,
                         const float* __restrict__ w,
                         float* __restrict__ out) {
    __shared__ float s_max[NPIX];
    __shared__ float s_avg[NPIX];
    __shared__ float s_attn[TH * TW];
    __shared__ float s_w[18];

    const int tid = threadIdx.x;
    const int b  = blockIdx.z;
    const int y0 = blockIdx.y * TH;
    const int x0 = blockIdx.x * TW;
    const float* __restrict__ xb = x + (size_t)b * C_ * H_ * W_;

    if (tid < 18) s_w[tid] = w[tid];

    // ---- Phase 1: channel mean+max over the 34x34 halo tile -------------
    int  off[KPP];
    bool val[KPP];
#pragma unroll
    for (int k = 0; k < KPP; k++) {
        int idx = tid + k * NT;
        val[k] = false; off[k] = 0;
        if (idx < NPIX) {
            int iy = idx / HW_;
            int ix = idx - iy * HW_;
            int Y = y0 - 1 + iy;
            int X = x0 - 1 + ix;
            if (Y >= 0 && Y < H_ && X >= 0 && X < W_) {
                val[k] = true;
                off[k] = Y * W_ + X;
            }
        }
    }

    float asum[KPP], amax[KPP];
#pragma unroll
    for (int k = 0; k < KPP; k++) { asum[k] = 0.0f; amax[k] = -1e30f; }

#pragma unroll 4
    for (int c = 0; c < C_; c++) {
        const float* __restrict__ xc = xb + (size_t)c * H_ * W_;
#pragma unroll
        for (int k = 0; k < KPP; k++) {
            if (val[k]) {
                float v = __ldg(xc + off[k]);   // default policy: keep in L2 for phase 3
                asum[k] += v;
                amax[k] = fmaxf(amax[k], v);
            }
        }
    }

#pragma unroll
    for (int k = 0; k < KPP; k++) {
        int idx = tid + k * NT;
        if (idx < NPIX) {
            s_avg[idx] = val[k] ? asum[k] * (1.0f / C_) : 0.0f;  // zero padding for conv
            s_max[idx] = val[k] ? amax[k] : 0.0f;
        }
    }
    __syncthreads();

    // ---- Phase 2: 3x3 conv (concat order [max, avg]) + sigmoid ----------
#pragma unroll
    for (int k = 0; k < 4; k++) {
        int p  = tid + k * NT;         // 0..1023
        int y  = p >> 5;
        int xq = p & 31;
        float acc = 0.0f;
#pragma unroll
        for (int dy = 0; dy < 3; dy++) {
#pragma unroll
            for (int dx = 0; dx < 3; dx++) {
                int hi = (y + dy) * HW_ + (xq + dx);
                acc += s_w[dy * 3 + dx]     * s_max[hi];   // w[0,0,:,:] -> max
                acc += s_w[9 + dy * 3 + dx] * s_avg[hi];   // w[0,1,:,:] -> avg
            }
        }
        s_attn[p] = 1.0f / (1.0f + expf(-acc));
    }
    __syncthreads();

    // ---- Phase 3: broadcast multiply, float4 vectorized -----------------
    const int p4 = tid * 4;
    const int y  = p4 >> 5;
    const int xq = p4 & 31;
    const size_t base = (size_t)(y0 + y) * W_ + (x0 + xq);
    const float4 a = *reinterpret_cast<const float4*>(&s_attn[p4]);
    float* __restrict__ ob = out + (size_t)b * C_ * H_ * W_;

#pragma unroll 4
    for (int c = 0; c < C_; c++) {
        const float4* src = reinterpret_cast<const float4*>(xb + (size_t)c * H_ * W_ + base);
        float4 v = __ldcs(src);          // last use: evict-first after read
        v.x *= a.x; v.y *= a.y; v.z *= a.z; v.w *= a.w;
        float4* dst = reinterpret_cast<float4*>(ob + (size_t)c * H_ * W_ + base);
        __stcs(dst, v);                  // streamed output: evict-first
    }
}

extern "C" void kernel_launch(void* const* d_in, const int* in_sizes, int n_in,
                              void* d_out, int out_size) {
    const float* x = (const float*)d_in[0];
    const float* w = (const float*)d_in[1];
    float* out     = (float*)d_out;

    // Allow the 80KB dynamic-smem occupancy pad (idempotent, cheap host call).
    cudaFuncSetAttribute(spatial_attention_kernel,
                         cudaFuncAttributeMaxDynamicSharedMemorySize, SMEM_PAD);

    dim3 grid(W_ / TW, H_ / TH, B_);   // (8, 8, 16) = 1024 blocks
    spatial_attention_kernel<<<grid, NT, SMEM_PAD>>>(x, w, out);
}

// round 3
// speedup vs baseline: 1.7046x; 1.7046x over previous
#include <cuda_runtime.h>
#include <math.h>

// x[16,64,256,256] f32, w[1,2,3,3] f32
#define B_   16
#define C_   64
#define H_   256
#define W_   256
#define TH   16
#define TW   32
#define HH_  (TH + 2)          // 18
#define HW_  (TW + 2)          // 34
#define NHALO (HH_ * HW_)      // 612
#define NINT  (TH * TW)        // 512
#define NT    1024
#define HWIMG (H_ * W_)        // 65536
#define CHW   (C_ * HWIMG)

// SMEM layout (floats):
//   s_x    [64 * 512]  = 32768
//   s_max  [612]
//   s_avg  [612]
//   s_attn [512]
//   s_w    [18]
#define OFF_MAX  (C_ * NINT)            // 32768
#define OFF_AVG  (OFF_MAX + NHALO)      // 33380
#define OFF_ATTN (OFF_AVG + NHALO)      // 33992  (16B aligned)
#define OFF_W    (OFF_ATTN + NINT)      // 34504
#define SMEM_FLOATS (OFF_W + 18 + 2)    // pad to even
#define SMEM_BYTES (SMEM_FLOATS * 4)    // ~138 KB

__global__ void __launch_bounds__(NT, 1)
spatial_attention_kernel(const float* __restrict__ x,
                         const float* __restrict__ w,
                         float* __restrict__ out) {
    extern __shared__ float smem[];
    float* __restrict__ s_x    = smem;
    float* __restrict__ s_max  = smem + OFF_MAX;
    float* __restrict__ s_avg  = smem + OFF_AVG;
    float* __restrict__ s_attn = smem + OFF_ATTN;
    float* __restrict__ s_w    = smem + OFF_W;

    const int tid = threadIdx.x;
    const int b   = blockIdx.z;
    const int y0  = blockIdx.y * TH;
    const int x0  = blockIdx.x * TW;
    const float* __restrict__ xb = x + (size_t)b * CHW;

    if (tid < 18) s_w[tid] = w[tid];

    // ---- Phase 1: stream tile once; pooled maps + SMEM-resident x -------
    // Threads 0..611 each own one halo pixel, loop all 64 channels.
    if (tid < NHALO) {
        const int iy = tid / HW_;
        const int ix = tid - iy * HW_;
        const int Y  = y0 - 1 + iy;
        const int X  = x0 - 1 + ix;
        const bool inb = (Y >= 0) & (Y < H_) & (X >= 0) & (X < W_);
        const bool interior = (iy >= 1) & (iy < HH_ - 1) & (ix >= 1) & (ix < HW_ - 1);
        const int  ipix = (iy - 1) * TW + (ix - 1);
        const size_t goff = (size_t)Y * W_ + X;

        float sum = 0.0f, mx = -1e30f;
        if (inb) {
            const float* __restrict__ p = xb + goff;
#pragma unroll 8
            for (int c = 0; c < C_; c++) {
                float v = __ldg(p + (size_t)c * HWIMG);
                sum += v;
                mx = fmaxf(mx, v);
                if (interior) s_x[c * NINT + ipix] = v;
            }
        }
        s_avg[tid] = inb ? sum * (1.0f / C_) : 0.0f;  // zero-pad for conv
        s_max[tid] = inb ? mx : 0.0f;
    }
    __syncthreads();

    // ---- Phase 2: 3x3 conv (concat [max, avg]) + sigmoid ---------------
    if (tid < NINT) {
        const int y  = tid >> 5;
        const int xq = tid & 31;
        float acc = 0.0f;
#pragma unroll
        for (int dy = 0; dy < 3; dy++) {
#pragma unroll
            for (int dx = 0; dx < 3; dx++) {
                const int hi = (y + dy) * HW_ + (xq + dx);
                acc += s_w[dy * 3 + dx]     * s_max[hi];
                acc += s_w[9 + dy * 3 + dx] * s_avg[hi];
            }
        }
        s_attn[tid] = 1.0f / (1.0f + expf(-acc));
    }
    __syncthreads();

    // ---- Phase 3: multiply from SMEM, float4 stores --------------------
    // tid -> (c0 = tid>>7 in 0..7, g = tid&127 float4-group), 8 channel passes.
    const int g  = tid & 127;            // 0..127 (512/4 groups)
    const int c0 = tid >> 7;             // 0..7
    const int py = g >> 3;               // row 0..15
    const int px = (g & 7) * 4;          // col 0,4,..,28
    const float4 a = *reinterpret_cast<const float4*>(&s_attn[py * TW + px]);
    const size_t obase = (size_t)b * CHW + (size_t)(y0 + py) * W_ + (x0 + px);

#pragma unroll
    for (int cc = 0; cc < C_; cc += 8) {
        const int c = cc + c0;
        float4 v = *reinterpret_cast<const float4*>(&s_x[c * NINT + g * 4]);
        v.x *= a.x; v.y *= a.y; v.z *= a.z; v.w *= a.w;
        __stcs(reinterpret_cast<float4*>(out + obase + (size_t)c * HWIMG), v);
    }
}

extern "C" void kernel_launch(void* const* d_in, const int* in_sizes, int n_in,
                              void* d_out, int out_size) {
    const float* x = (const float*)d_in[0];
    const float* w = (const float*)d_in[1];
    float* out     = (float*)d_out;

    cudaFuncSetAttribute(spatial_attention_kernel,
                         cudaFuncAttributeMaxDynamicSharedMemorySize, SMEM_BYTES);

    dim3 grid(W_ / TW, H_ / TH, B_);   // (8, 16, 16) = 2048 blocks
    spatial_attention_kernel<<<grid, NT, SMEM_BYTES>>>(x, w, out);
}